// round 1
// baseline (speedup 1.0000x reference)
#include <cuda_runtime.h>

// CrossAttUnit: fused per-segment cross attention.
// Shapes (fixed for this problem): N=262144 tokens, H=256, D=64, L=seg_len=64, B=N/L=4096.
// out[b,l,m] = colnorm_l( softmax_m( (1/sqrt(D)) * (y_b @ k) @ (yhat_b @ q)^T ) + 1e-6 )

#define HDIM 256
#define DDIM 64
#define LSEG 64
#define PAD  68          // smem row pitch (floats), 16B-aligned

__global__ __launch_bounds__(256, 2)
void cross_att_kernel(const float* __restrict__ yhat,
                      const float* __restrict__ y,
                      const float* __restrict__ kmat,
                      const float* __restrict__ qmat,
                      float* __restrict__ out)
{
    extern __shared__ float smem[];
    float* a0 = smem;                 // y chunk  [64][PAD], later yk [64][PAD]
    float* a1 = a0 + 64 * PAD;        // yhat chunk,        later yq
    float* w0 = a1 + 64 * PAD;        // k chunk,           later M (attn)
    float* w1 = w0 + 64 * PAD;        // q chunk
    __shared__ float csum_inv[64];

    const int tid  = threadIdx.x;
    const int seg  = blockIdx.x;
    const int half = tid >> 7;        // 0: compute yk from (y,k); 1: yq from (yhat,q)
    const int htid = tid & 127;
    const int ty   = htid >> 4;       // 0..7  -> rows ty*8 .. ty*8+7
    const int tx   = htid & 15;       // 0..15 -> cols tx*4 .. tx*4+3

    const float* amat = half ? yhat : y;
    const float* wmat = half ? qmat : kmat;
    float* a_t = half ? a1 : a0;
    float* w_t = half ? w1 : w0;

    // ---------------- Phase 1: projections yk = y@k, yq = yhat@q ----------------
    float acc[8][4];
    #pragma unroll
    for (int j = 0; j < 8; j++)
        #pragma unroll
        for (int n = 0; n < 4; n++) acc[j][n] = 0.0f;

    const long base = (long)seg * LSEG * HDIM;

    #pragma unroll 1
    for (int c = 0; c < HDIM / 64; c++) {
        // load 64x64 fp32 tiles (this half loads its own A-chunk and W-chunk)
        #pragma unroll
        for (int j = 0; j < 8; j++) {
            const int i = ty + j * 8;
            float4 va = *(const float4*)&amat[base + (long)i * HDIM + c * 64 + tx * 4];
            *(float4*)&a_t[i * PAD + tx * 4] = va;
            float4 vw = *(const float4*)&wmat[(c * 64 + i) * DDIM + tx * 4];
            *(float4*)&w_t[i * PAD + tx * 4] = vw;
        }
        __syncthreads();

        #pragma unroll 4
        for (int kk = 0; kk < 64; kk++) {
            const float4 b = *(const float4*)&w_t[kk * PAD + tx * 4];
            #pragma unroll
            for (int j = 0; j < 8; j++) {
                const float a = a_t[(ty * 8 + j) * PAD + kk];
                acc[j][0] += a * b.x;
                acc[j][1] += a * b.y;
                acc[j][2] += a * b.z;
                acc[j][3] += a * b.w;
            }
        }
        __syncthreads();
    }

    // write yk into a0, yq into a1 (reuse chunk space)
    #pragma unroll
    for (int j = 0; j < 8; j++) {
        float4 v = make_float4(acc[j][0], acc[j][1], acc[j][2], acc[j][3]);
        *(float4*)&a_t[(ty * 8 + j) * PAD + tx * 4] = v;
    }
    __syncthreads();

    // ---------------- Phase 2: M[l][m] = (1/8) * sum_d yk[l][d]*yq[m][d] ----------------
    // thread (ty2, tx2) owns rows l = ty2 + 16j, cols m = tx2 + 16n (strided to dodge bank conflicts)
    {
        const int ty2 = tid >> 4;     // 0..15
        const int tx2 = tid & 15;     // 0..15
        float m_acc[4][4];
        #pragma unroll
        for (int j = 0; j < 4; j++)
            #pragma unroll
            for (int n = 0; n < 4; n++) m_acc[j][n] = 0.0f;

        #pragma unroll 2
        for (int d = 0; d < DDIM; d += 4) {
            float4 av[4], bv[4];
            #pragma unroll
            for (int j = 0; j < 4; j++) av[j] = *(const float4*)&a0[(ty2 + 16 * j) * PAD + d];
            #pragma unroll
            for (int n = 0; n < 4; n++) bv[n] = *(const float4*)&a1[(tx2 + 16 * n) * PAD + d];
            #pragma unroll
            for (int j = 0; j < 4; j++)
                #pragma unroll
                for (int n = 0; n < 4; n++) {
                    m_acc[j][n] += av[j].x * bv[n].x;
                    m_acc[j][n] += av[j].y * bv[n].y;
                    m_acc[j][n] += av[j].z * bv[n].z;
                    m_acc[j][n] += av[j].w * bv[n].w;
                }
        }
        const float scale = 0.125f;   // 1/sqrt(64)
        #pragma unroll
        for (int j = 0; j < 4; j++)
            #pragma unroll
            for (int n = 0; n < 4; n++)
                w0[(ty2 + 16 * j) * PAD + (tx2 + 16 * n)] = m_acc[j][n] * scale;
    }
    __syncthreads();

    // ---------------- Phase 3: row softmax (over m) + EPS ----------------
    {
        const int warp = tid >> 5, lane = tid & 31;
        #pragma unroll 1
        for (int rr = 0; rr < 8; rr++) {
            const int r = warp * 8 + rr;
            float v0 = w0[r * PAD + lane];
            float v1 = w0[r * PAD + lane + 32];
            float mx = fmaxf(v0, v1);
            #pragma unroll
            for (int o = 16; o > 0; o >>= 1)
                mx = fmaxf(mx, __shfl_xor_sync(0xffffffffu, mx, o));
            float e0 = __expf(v0 - mx);
            float e1 = __expf(v1 - mx);
            float s = e0 + e1;
            #pragma unroll
            for (int o = 16; o > 0; o >>= 1)
                s += __shfl_xor_sync(0xffffffffu, s, o);
            const float inv = 1.0f / s;
            w0[r * PAD + lane]      = e0 * inv + 1e-6f;
            w0[r * PAD + lane + 32] = e1 * inv + 1e-6f;
        }
    }
    __syncthreads();

    // ---------------- Phase 4: column sums (over l) ----------------
    if (tid < 64) {
        float s = 0.0f;
        #pragma unroll 8
        for (int l = 0; l < 64; l++) s += w0[l * PAD + tid];
        csum_inv[tid] = 1.0f / s;
    }
    __syncthreads();

    // ---------------- Phase 5: normalize + coalesced store ----------------
    {
        float* outb = out + (long)seg * (LSEG * LSEG);
        #pragma unroll
        for (int e = 0; e < 4; e++) {
            const int f4 = e * 256 + tid;       // float4 index in [0,1024)
            const int l  = f4 >> 4;
            const int m0 = (f4 & 15) * 4;
            float4 v = *(const float4*)&w0[l * PAD + m0];
            v.x *= csum_inv[m0 + 0];
            v.y *= csum_inv[m0 + 1];
            v.z *= csum_inv[m0 + 2];
            v.w *= csum_inv[m0 + 3];
            *(float4*)&outb[l * 64 + m0] = v;
        }
    }
}

extern "C" void kernel_launch(void* const* d_in, const int* in_sizes, int n_in,
                              void* d_out, int out_size)
{
    const float* yhat = (const float*)d_in[0];   // yhat_embedding [N, 256]
    const float* y    = (const float*)d_in[1];   // y_embedding    [N, 256]
    const float* kmat = (const float*)d_in[2];   // k [256, 64]
    const float* qmat = (const float*)d_in[3];   // q [256, 64]
    float* out = (float*)d_out;                  // [B, 64, 64]

    const int N = in_sizes[1] / HDIM;            // tokens
    const int B = N / LSEG;                      // segments

    const size_t smem_bytes = 4 * 64 * PAD * sizeof(float);  // 69632
    cudaFuncSetAttribute(cross_att_kernel,
                         cudaFuncAttributeMaxDynamicSharedMemorySize,
                         (int)smem_bytes);

    cross_att_kernel<<<B, 256, smem_bytes>>>(yhat, y, kmat, qmat, out);
}

// round 3
// speedup vs baseline: 1.7437x; 1.7437x over previous
#include <cuda_runtime.h>
#include <cuda_fp16.h>
#include <cstdint>

// CrossAttUnit fused — fp16-split (Ootomo) warp MMA version (baseline PTX only,
// no sm_103a-specific instructions; harness PTX stage targets compute_103).
// N=262144, H=256, D=64, L=64, B=4096. 1 segment per CTA, 128 threads (4 warps).

#define HDIM 256
#define PITCH 72            // smem half pitch: 144B = 36 words = 4 mod 32 banks -> LDSM conflict-free
#define FPITCH 68           // fp32 attn pitch

// smem half-index offsets
#define AY_HI 0u
#define AY_LO 4608u
#define AH_HI 9216u
#define AH_LO 13824u
#define B_BASE 18432u       // 4 buffers of 4608 halfs: bKhi, bKlo, bQhi, bQlo
#define SMEM_HALFS 36864u   // 73728 bytes

__device__ __align__(16) __half g_b[2 * 2 * 256 * 64];  // [mat*2+split][k][n]

__global__ void split_kq_kernel(const float* __restrict__ kmat,
                                const float* __restrict__ qmat) {
    int gid = blockIdx.x * 256 + threadIdx.x;        // 32768
    int mat = gid >> 14, k = (gid >> 6) & 255, n = gid & 63;
    float x = mat ? qmat[k * 64 + n] : kmat[k * 64 + n];
    __half hi = __float2half_rn(x);
    __half lo = __float2half_rn(x - __half2float(hi));
    g_b[(mat * 2 + 0) * 16384 + k * 64 + n] = hi;
    g_b[(mat * 2 + 1) * 16384 + k * 64 + n] = lo;
}

__device__ __forceinline__ uint32_t smem_u32(const void* p) {
    uint32_t a;
    asm("{ .reg .u64 t; cvta.to.shared.u64 t, %1; cvt.u32.u64 %0, t; }" : "=r"(a) : "l"(p));
    return a;
}

__device__ __forceinline__ void ldsm4(uint32_t r[4], uint32_t addr) {
    asm volatile("ldmatrix.sync.aligned.m8n8.x4.shared.b16 {%0,%1,%2,%3}, [%4];"
                 : "=r"(r[0]), "=r"(r[1]), "=r"(r[2]), "=r"(r[3]) : "r"(addr));
}
__device__ __forceinline__ void ldsm4t(uint32_t r[4], uint32_t addr) {
    asm volatile("ldmatrix.sync.aligned.m8n8.x4.trans.shared.b16 {%0,%1,%2,%3}, [%4];"
                 : "=r"(r[0]), "=r"(r[1]), "=r"(r[2]), "=r"(r[3]) : "r"(addr));
}
__device__ __forceinline__ void mma16816(float c[4], const uint32_t a[4],
                                         uint32_t b0, uint32_t b1) {
    asm volatile(
        "mma.sync.aligned.m16n8k16.row.col.f32.f16.f16.f32 "
        "{%0,%1,%2,%3},{%4,%5,%6,%7},{%8,%9},{%0,%1,%2,%3};"
        : "+f"(c[0]), "+f"(c[1]), "+f"(c[2]), "+f"(c[3])
        : "r"(a[0]), "r"(a[1]), "r"(a[2]), "r"(a[3]), "r"(b0), "r"(b1));
}

__device__ __forceinline__ void split2(float x0, float x1, uint32_t& hi, uint32_t& lo) {
    __half h0 = __float2half_rn(x0), h1 = __float2half_rn(x1);
    __half l0 = __float2half_rn(x0 - __half2float(h0));
    __half l1 = __float2half_rn(x1 - __half2float(h1));
    __half2 H = __halves2half2(h0, h1), L = __halves2half2(l0, l1);
    hi = *(uint32_t*)&H;
    lo = *(uint32_t*)&L;
}

// ldmatrix address helpers (tile base = half-index of [row0][col0], lane-specific)
__device__ __forceinline__ uint32_t addrA(uint32_t sb, uint32_t tile_halfs, int lane) {
    // A (and GEMM2-B) 16x16 row-major: lanes0-15 rows, col 0; lanes16-31 rows, col 8
    int row = lane & 15, colh = (lane >> 4) << 3;
    return sb + (tile_halfs + row * PITCH + colh) * 2;
}
__device__ __forceinline__ uint32_t addrBt(uint32_t sb, uint32_t tile_halfs, int lane) {
    // B trans 16(k)x16(n): q=lane/8: k += (q&1)*8 + i, n += (q>>1)*8
    int q = lane >> 3, i = lane & 7;
    int k = i + ((q & 1) << 3), n = (q >> 1) << 3;
    return sb + (tile_halfs + k * PITCH + n) * 2;
}

__global__ __launch_bounds__(128)
void cross_att_hmma(const float* __restrict__ yhat,
                    const float* __restrict__ y,
                    float* __restrict__ out) {
    extern __shared__ __half smem[];
    const uint32_t sb = smem_u32(smem);
    const int tid = threadIdx.x, wid = tid >> 5, lane = tid & 31;
    __shared__ float csum_inv[64];

    const long rowbase = (long)blockIdx.x * 64;

    float ck[8][4], cq[8][4];
    #pragma unroll
    for (int n = 0; n < 8; n++)
        #pragma unroll
        for (int j = 0; j < 4; j++) { ck[n][j] = 0.0f; cq[n][j] = 0.0f; }

    // ---------------- GEMM1: yk = y@k, yq = yhat@q ; K streamed in 4 chunks ----------------
    #pragma unroll 1
    for (int c = 0; c < 4; c++) {
        // stage A: y / yhat chunk [64 rows][64 cols] fp32 -> hi/lo fp16
        #pragma unroll
        for (int t = 0; t < 8; t++) {
            const int idx = tid + t * 128;          // 0..1023
            const int row = idx >> 4, c4 = idx & 15;
            const long g = (rowbase + row) * HDIM + c * 64 + c4 * 4;
            float4 vy = *(const float4*)&y[g];
            float4 vh = *(const float4*)&yhat[g];
            uint2 yh, yl, hh, hl;
            split2(vy.x, vy.y, yh.x, yl.x); split2(vy.z, vy.w, yh.y, yl.y);
            split2(vh.x, vh.y, hh.x, hl.x); split2(vh.z, vh.w, hh.y, hl.y);
            const uint32_t so = (uint32_t)(row * PITCH + c4 * 4);
            *(uint2*)&smem[AY_HI + so] = yh;
            *(uint2*)&smem[AY_LO + so] = yl;
            *(uint2*)&smem[AH_HI + so] = hh;
            *(uint2*)&smem[AH_LO + so] = hl;
        }
        // stage B: 4 pre-split fp16 buffers [64k][64n]
        #pragma unroll
        for (int t = 0; t < 16; t++) {
            const int idx = tid + t * 128;          // 0..2047
            const int buf = idx >> 9, rem = idx & 511;
            const int row = rem >> 3, u4 = rem & 7;
            uint4 v = *(const uint4*)&g_b[buf * 16384 + (c * 64 + row) * 64 + u4 * 8];
            *(uint4*)&smem[B_BASE + buf * 4608u + (uint32_t)(row * PITCH + u4 * 8)] = v;
        }
        __syncthreads();

        #pragma unroll
        for (int ks = 0; ks < 4; ks++) {
            uint32_t aYh[4], aYl[4], aHh[4], aHl[4];
            const uint32_t at = (uint32_t)(wid * 16 * PITCH + ks * 16);
            ldsm4(aYh, addrA(sb, AY_HI + at, lane));
            ldsm4(aYl, addrA(sb, AY_LO + at, lane));
            ldsm4(aHh, addrA(sb, AH_HI + at, lane));
            ldsm4(aHl, addrA(sb, AH_LO + at, lane));
            #pragma unroll
            for (int np = 0; np < 4; np++) {
                const uint32_t bt = (uint32_t)(ks * 16 * PITCH + np * 16);
                uint32_t kH[4], kL[4], qH[4], qL[4];
                ldsm4t(kH, addrBt(sb, B_BASE + 0u * 4608u + bt, lane));
                ldsm4t(kL, addrBt(sb, B_BASE + 1u * 4608u + bt, lane));
                ldsm4t(qH, addrBt(sb, B_BASE + 2u * 4608u + bt, lane));
                ldsm4t(qL, addrBt(sb, B_BASE + 3u * 4608u + bt, lane));
                // n-tile 2np uses regs {0,1}; n-tile 2np+1 uses {2,3}
                mma16816(ck[2 * np],     aYh, kH[0], kH[1]);
                mma16816(ck[2 * np],     aYh, kL[0], kL[1]);
                mma16816(ck[2 * np],     aYl, kH[0], kH[1]);
                mma16816(ck[2 * np + 1], aYh, kH[2], kH[3]);
                mma16816(ck[2 * np + 1], aYh, kL[2], kL[3]);
                mma16816(ck[2 * np + 1], aYl, kH[2], kH[3]);
                mma16816(cq[2 * np],     aHh, qH[0], qH[1]);
                mma16816(cq[2 * np],     aHh, qL[0], qL[1]);
                mma16816(cq[2 * np],     aHl, qH[0], qH[1]);
                mma16816(cq[2 * np + 1], aHh, qH[2], qH[3]);
                mma16816(cq[2 * np + 1], aHh, qL[2], qL[3]);
                mma16816(cq[2 * np + 1], aHl, qH[2], qH[3]);
            }
        }
        __syncthreads();
    }

    // ---------------- split yk/yq -> smem (reuse B region) ----------------
    // yk_hi = B+0, yk_lo = B+1, yq_hi = B+2, yq_lo = B+3 (each [64][PITCH])
    {
        const int r0 = wid * 16 + (lane >> 2);
        const int col = (lane & 3) * 2;
        #pragma unroll
        for (int nt = 0; nt < 8; nt++) {
            uint32_t hi, lo;
            split2(ck[nt][0], ck[nt][1], hi, lo);
            *(uint32_t*)&smem[B_BASE + 0u * 4608u + (uint32_t)(r0 * PITCH + nt * 8 + col)] = hi;
            *(uint32_t*)&smem[B_BASE + 1u * 4608u + (uint32_t)(r0 * PITCH + nt * 8 + col)] = lo;
            split2(ck[nt][2], ck[nt][3], hi, lo);
            *(uint32_t*)&smem[B_BASE + 0u * 4608u + (uint32_t)((r0 + 8) * PITCH + nt * 8 + col)] = hi;
            *(uint32_t*)&smem[B_BASE + 1u * 4608u + (uint32_t)((r0 + 8) * PITCH + nt * 8 + col)] = lo;
            split2(cq[nt][0], cq[nt][1], hi, lo);
            *(uint32_t*)&smem[B_BASE + 2u * 4608u + (uint32_t)(r0 * PITCH + nt * 8 + col)] = hi;
            *(uint32_t*)&smem[B_BASE + 3u * 4608u + (uint32_t)(r0 * PITCH + nt * 8 + col)] = lo;
            split2(cq[nt][2], cq[nt][3], hi, lo);
            *(uint32_t*)&smem[B_BASE + 2u * 4608u + (uint32_t)((r0 + 8) * PITCH + nt * 8 + col)] = hi;
            *(uint32_t*)&smem[B_BASE + 3u * 4608u + (uint32_t)((r0 + 8) * PITCH + nt * 8 + col)] = lo;
        }
    }
    __syncthreads();

    // ---------------- GEMM2: M = yk @ yq^T  (A=yk row-major, B=yq row-major [n][k]) ----------------
    float cm[8][4];
    #pragma unroll
    for (int n = 0; n < 8; n++)
        #pragma unroll
        for (int j = 0; j < 4; j++) cm[n][j] = 0.0f;

    #pragma unroll
    for (int ks = 0; ks < 4; ks++) {
        uint32_t Ah[4], Al[4];
        const uint32_t at = (uint32_t)(wid * 16 * PITCH + ks * 16);
        ldsm4(Ah, addrA(sb, B_BASE + 0u * 4608u + at, lane));
        ldsm4(Al, addrA(sb, B_BASE + 1u * 4608u + at, lane));
        #pragma unroll
        for (int np = 0; np < 4; np++) {
            // non-trans x4 on yq[n0..n0+15][k0..k0+15]: r0=b0(n-tile 2np), r1=b0(2np+1), r2=b1(2np), r3=b1(2np+1)
            const uint32_t bt = (uint32_t)(np * 16 * PITCH + ks * 16);
            uint32_t Bh[4], Bl[4];
            ldsm4(Bh, addrA(sb, B_BASE + 2u * 4608u + bt, lane));
            ldsm4(Bl, addrA(sb, B_BASE + 3u * 4608u + bt, lane));
            mma16816(cm[2 * np],     Ah, Bh[0], Bh[2]);
            mma16816(cm[2 * np],     Ah, Bl[0], Bl[2]);
            mma16816(cm[2 * np],     Al, Bh[0], Bh[2]);
            mma16816(cm[2 * np + 1], Ah, Bh[1], Bh[3]);
            mma16816(cm[2 * np + 1], Ah, Bl[1], Bl[3]);
            mma16816(cm[2 * np + 1], Al, Bh[1], Bh[3]);
        }
    }
    __syncthreads();   // done reading yk/yq; attn region (AY) free to write

    // ---------------- epilogue: row softmax + EPS -> attn smem ----------------
    float* attnf = (float*)smem;     // [64][FPITCH]
    {
        const float scale = 0.125f;
        #pragma unroll
        for (int part = 0; part < 2; part++) {       // rows r0 and r0+8
            const int row = wid * 16 + (lane >> 2) + part * 8;
            float v[16];
            #pragma unroll
            for (int nt = 0; nt < 8; nt++) {
                v[2 * nt]     = cm[nt][2 * part];
                v[2 * nt + 1] = cm[nt][2 * part + 1];
            }
            float mx = v[0];
            #pragma unroll
            for (int j = 1; j < 16; j++) mx = fmaxf(mx, v[j]);
            mx = fmaxf(mx, __shfl_xor_sync(0xffffffffu, mx, 1));
            mx = fmaxf(mx, __shfl_xor_sync(0xffffffffu, mx, 2));
            float s = 0.0f;
            #pragma unroll
            for (int j = 0; j < 16; j++) { v[j] = __expf((v[j] - mx) * scale); s += v[j]; }
            s += __shfl_xor_sync(0xffffffffu, s, 1);
            s += __shfl_xor_sync(0xffffffffu, s, 2);
            const float inv = 1.0f / s;
            const int colb = (lane & 3) * 2;
            #pragma unroll
            for (int nt = 0; nt < 8; nt++) {
                float2 w2 = make_float2(v[2 * nt] * inv + 1e-6f, v[2 * nt + 1] * inv + 1e-6f);
                *(float2*)&attnf[row * FPITCH + nt * 8 + colb] = w2;
            }
        }
    }
    __syncthreads();

    // ---------------- column sums + normalize + store ----------------
    if (tid < 64) {
        float s = 0.0f;
        #pragma unroll 8
        for (int l = 0; l < 64; l++) s += attnf[l * FPITCH + tid];
        csum_inv[tid] = 1.0f / s;
    }
    __syncthreads();

    {
        float* outb = out + (long)blockIdx.x * 4096;
        #pragma unroll
        for (int e = 0; e < 8; e++) {
            const int f4 = e * 128 + tid;
            const int l = f4 >> 4, m0 = (f4 & 15) * 4;
            float4 v = *(const float4*)&attnf[l * FPITCH + m0];
            v.x *= csum_inv[m0 + 0];
            v.y *= csum_inv[m0 + 1];
            v.z *= csum_inv[m0 + 2];
            v.w *= csum_inv[m0 + 3];
            *(float4*)&outb[l * 64 + m0] = v;
        }
    }
}

extern "C" void kernel_launch(void* const* d_in, const int* in_sizes, int n_in,
                              void* d_out, int out_size) {
    const float* yhat = (const float*)d_in[0];
    const float* y    = (const float*)d_in[1];
    const float* kmat = (const float*)d_in[2];
    const float* qmat = (const float*)d_in[3];
    float* out = (float*)d_out;

    const int N = in_sizes[1] / HDIM;
    const int grid = N / 64;                 // 1 segment per CTA

    split_kq_kernel<<<128, 256>>>(kmat, qmat);

    const size_t smem_bytes = SMEM_HALFS * sizeof(__half);   // 73728
    cudaFuncSetAttribute(cross_att_hmma,
                         cudaFuncAttributeMaxDynamicSharedMemorySize, (int)smem_bytes);
    cross_att_hmma<<<grid, 128, smem_bytes>>>(yhat, y, out);
}

// round 4
// speedup vs baseline: 2.1544x; 1.2356x over previous
#include <cuda_runtime.h>
#include <cuda_fp16.h>
#include <cstdint>

// CrossAttUnit fused — fp16-split (Ootomo) warp MMA, 8-warp CTA version.
// N=262144, H=256, D=64, L=64, B=4096. 1 segment per CTA, 256 threads.
// Baseline-PTX only (mma.sync + ldmatrix + cp.async); no sm_103a-specific ops.

#define HDIM 256
#define PITCH 72            // smem half pitch per tile row (conflict-free LDSM)
#define FPITCH 68           // fp32 logits/attn pitch

// smem half-index offsets
#define AY_HI 0u
#define AY_LO 4608u
#define AH_HI 9216u
#define AH_LO 13824u
#define B_BASE 18432u       // 4 bufs of 4608 halfs: GEMM1 = bKhi,bKlo,bQhi,bQlo; GEMM2 = ykhi,yklo,yqhi,yqlo
#define SMEM_HALFS 36864u   // 73728 bytes dynamic

__device__ __align__(16) __half g_b[2 * 2 * 256 * 64];  // [mat*2+split][k][n]

__global__ void split_kq_kernel(const float* __restrict__ kmat,
                                const float* __restrict__ qmat) {
    int gid = blockIdx.x * 256 + threadIdx.x;        // 32768
    int mat = gid >> 14, k = (gid >> 6) & 255, n = gid & 63;
    float x = mat ? qmat[k * 64 + n] : kmat[k * 64 + n];
    __half hi = __float2half_rn(x);
    __half lo = __float2half_rn(x - __half2float(hi));
    g_b[(mat * 2 + 0) * 16384 + k * 64 + n] = hi;
    g_b[(mat * 2 + 1) * 16384 + k * 64 + n] = lo;
}

__device__ __forceinline__ uint32_t smem_u32(const void* p) {
    uint32_t a;
    asm("{ .reg .u64 t; cvta.to.shared.u64 t, %1; cvt.u32.u64 %0, t; }" : "=r"(a) : "l"(p));
    return a;
}
__device__ __forceinline__ void ldsm4(uint32_t r[4], uint32_t addr) {
    asm volatile("ldmatrix.sync.aligned.m8n8.x4.shared.b16 {%0,%1,%2,%3}, [%4];"
                 : "=r"(r[0]), "=r"(r[1]), "=r"(r[2]), "=r"(r[3]) : "r"(addr));
}
__device__ __forceinline__ void ldsm4t(uint32_t r[4], uint32_t addr) {
    asm volatile("ldmatrix.sync.aligned.m8n8.x4.trans.shared.b16 {%0,%1,%2,%3}, [%4];"
                 : "=r"(r[0]), "=r"(r[1]), "=r"(r[2]), "=r"(r[3]) : "r"(addr));
}
__device__ __forceinline__ void mma16816(float c[4], const uint32_t a[4],
                                         uint32_t b0, uint32_t b1) {
    asm volatile(
        "mma.sync.aligned.m16n8k16.row.col.f32.f16.f16.f32 "
        "{%0,%1,%2,%3},{%4,%5,%6,%7},{%8,%9},{%0,%1,%2,%3};"
        : "+f"(c[0]), "+f"(c[1]), "+f"(c[2]), "+f"(c[3])
        : "r"(a[0]), "r"(a[1]), "r"(a[2]), "r"(a[3]), "r"(b0), "r"(b1));
}
__device__ __forceinline__ void split2(float x0, float x1, uint32_t& hi, uint32_t& lo) {
    __half h0 = __float2half_rn(x0), h1 = __float2half_rn(x1);
    __half l0 = __float2half_rn(x0 - __half2float(h0));
    __half l1 = __float2half_rn(x1 - __half2float(h1));
    __half2 H = __halves2half2(h0, h1), L = __halves2half2(l0, l1);
    hi = *(uint32_t*)&H;
    lo = *(uint32_t*)&L;
}
__device__ __forceinline__ uint32_t addrA(uint32_t sb, uint32_t tile_halfs, int lane) {
    int row = lane & 15, colh = (lane >> 4) << 3;
    return sb + (tile_halfs + row * PITCH + colh) * 2;
}
__device__ __forceinline__ uint32_t addrBt(uint32_t sb, uint32_t tile_halfs, int lane) {
    int q = lane >> 3, i = lane & 7;
    int k = i + ((q & 1) << 3), n = (q >> 1) << 3;
    return sb + (tile_halfs + k * PITCH + n) * 2;
}

#define CP_ASYNC16(saddr, gptr) \
    asm volatile("cp.async.cg.shared.global [%0], [%1], 16;" :: "r"(saddr), "l"(gptr) : "memory")
#define CP_COMMIT() asm volatile("cp.async.commit_group;" ::: "memory")
#define CP_WAIT0()  asm volatile("cp.async.wait_group 0;" ::: "memory")

__global__ __launch_bounds__(256, 3)
void cross_att_hmma8(const float* __restrict__ yhat,
                     const float* __restrict__ y,
                     float* __restrict__ out) {
    extern __shared__ __half smem[];
    const uint32_t sb = smem_u32(smem);
    const int tid = threadIdx.x, wid = tid >> 5, lane = tid & 31;
    __shared__ float part[4][64];
    __shared__ float csum_inv[64];

    const long rowbase = (long)blockIdx.x * 64;
    const int mat = wid >> 2;            // 0: yk (y, k) ; 1: yq (yhat, q)
    const int rt  = wid & 3;             // row tile (16 rows)

    float cc[8][4];
    #pragma unroll
    for (int n = 0; n < 8; n++)
        #pragma unroll
        for (int j = 0; j < 4; j++) cc[n][j] = 0.0f;

    const uint32_t A_HI = mat ? AH_HI : AY_HI;
    const uint32_t A_LO = mat ? AH_LO : AY_LO;
    const uint32_t Bb_HI = B_BASE + (mat ? 2u : 0u) * 4608u;
    const uint32_t Bb_LO = Bb_HI + 4608u;

    // ---------------- GEMM1: yk = y@k, yq = yhat@q ; K streamed in 4 chunks ----------------
    #pragma unroll 1
    for (int c = 0; c < 4; c++) {
        // B tiles via cp.async (pre-split fp16, gmem layout matches row layout)
        #pragma unroll
        for (int t = 0; t < 8; t++) {
            const int idx = tid + t * 256;          // 0..2047
            const int buf = idx >> 9, rem = idx & 511;
            const int row = rem >> 3, u4 = rem & 7;
            const uint32_t sa = sb + (B_BASE + buf * 4608u + (uint32_t)(row * PITCH + u4 * 8)) * 2;
            CP_ASYNC16(sa, &g_b[buf * 16384 + (c * 64 + row) * 64 + u4 * 8]);
        }
        CP_COMMIT();
        // A: y / yhat chunk fp32 -> hi/lo fp16 (through registers)
        #pragma unroll
        for (int t = 0; t < 4; t++) {
            const int idx = tid + t * 256;          // 0..1023
            const int row = idx >> 4, c4 = idx & 15;
            const long g = (rowbase + row) * HDIM + c * 64 + c4 * 4;
            float4 vy = *(const float4*)&y[g];
            float4 vh = *(const float4*)&yhat[g];
            uint2 yh, yl, hh, hl;
            split2(vy.x, vy.y, yh.x, yl.x); split2(vy.z, vy.w, yh.y, yl.y);
            split2(vh.x, vh.y, hh.x, hl.x); split2(vh.z, vh.w, hh.y, hl.y);
            const uint32_t so = (uint32_t)(row * PITCH + c4 * 4);
            *(uint2*)&smem[AY_HI + so] = yh;
            *(uint2*)&smem[AY_LO + so] = yl;
            *(uint2*)&smem[AH_HI + so] = hh;
            *(uint2*)&smem[AH_LO + so] = hl;
        }
        CP_WAIT0();
        __syncthreads();

        #pragma unroll
        for (int ks = 0; ks < 4; ks++) {
            uint32_t ah[4], al[4];
            const uint32_t at = (uint32_t)(rt * 16 * PITCH + ks * 16);
            ldsm4(ah, addrA(sb, A_HI + at, lane));
            ldsm4(al, addrA(sb, A_LO + at, lane));
            #pragma unroll
            for (int np = 0; np < 4; np++) {
                const uint32_t bt = (uint32_t)(ks * 16 * PITCH + np * 16);
                uint32_t bh[4], bl[4];
                ldsm4t(bh, addrBt(sb, Bb_HI + bt, lane));
                ldsm4t(bl, addrBt(sb, Bb_LO + bt, lane));
                mma16816(cc[2 * np],     ah, bh[0], bh[1]);
                mma16816(cc[2 * np],     ah, bl[0], bl[1]);
                mma16816(cc[2 * np],     al, bh[0], bh[1]);
                mma16816(cc[2 * np + 1], ah, bh[2], bh[3]);
                mma16816(cc[2 * np + 1], ah, bl[2], bl[3]);
                mma16816(cc[2 * np + 1], al, bh[2], bh[3]);
            }
        }
        __syncthreads();
    }

    // ---------------- split yk/yq -> B region (yk: bufs 0/1, yq: bufs 2/3) ----------------
    {
        const int r0 = rt * 16 + (lane >> 2);
        const int col = (lane & 3) * 2;
        const uint32_t HIb = B_BASE + (mat ? 2u : 0u) * 4608u;
        const uint32_t LOb = HIb + 4608u;
        #pragma unroll
        for (int nt = 0; nt < 8; nt++) {
            uint32_t hi, lo;
            split2(cc[nt][0], cc[nt][1], hi, lo);
            *(uint32_t*)&smem[HIb + (uint32_t)(r0 * PITCH + nt * 8 + col)] = hi;
            *(uint32_t*)&smem[LOb + (uint32_t)(r0 * PITCH + nt * 8 + col)] = lo;
            split2(cc[nt][2], cc[nt][3], hi, lo);
            *(uint32_t*)&smem[HIb + (uint32_t)((r0 + 8) * PITCH + nt * 8 + col)] = hi;
            *(uint32_t*)&smem[LOb + (uint32_t)((r0 + 8) * PITCH + nt * 8 + col)] = lo;
        }
    }
    __syncthreads();

    // ---------------- GEMM2: M = yk @ yq^T ; warp = (row tile rt, col half ch) ----------------
    float* attnf = (float*)smem;                 // logits [64][FPITCH], aliases A region
    {
        const int ch = wid >> 2;                 // 0 or 1 -> cols ch*32..+32
        const int ct = ch * 32;
        float cm[4][4];
        #pragma unroll
        for (int n = 0; n < 4; n++)
            #pragma unroll
            for (int j = 0; j < 4; j++) cm[n][j] = 0.0f;

        #pragma unroll
        for (int ks = 0; ks < 4; ks++) {
            uint32_t Ah[4], Al[4];
            const uint32_t at = (uint32_t)(rt * 16 * PITCH + ks * 16);
            ldsm4(Ah, addrA(sb, B_BASE + 0u * 4608u + at, lane));
            ldsm4(Al, addrA(sb, B_BASE + 1u * 4608u + at, lane));
            #pragma unroll
            for (int nl = 0; nl < 2; nl++) {
                const uint32_t bt = (uint32_t)((ct + nl * 16) * PITCH + ks * 16);
                uint32_t Bh[4], Bl[4];
                ldsm4(Bh, addrA(sb, B_BASE + 2u * 4608u + bt, lane));
                ldsm4(Bl, addrA(sb, B_BASE + 3u * 4608u + bt, lane));
                mma16816(cm[2 * nl],     Ah, Bh[0], Bh[2]);
                mma16816(cm[2 * nl],     Ah, Bl[0], Bl[2]);
                mma16816(cm[2 * nl],     Al, Bh[0], Bh[2]);
                mma16816(cm[2 * nl + 1], Ah, Bh[1], Bh[3]);
                mma16816(cm[2 * nl + 1], Ah, Bl[1], Bl[3]);
                mma16816(cm[2 * nl + 1], Al, Bh[1], Bh[3]);
            }
        }
        __syncthreads();   // A region free; write scaled logits

        const int r0 = rt * 16 + (lane >> 2);
        const int cb = (lane & 3) * 2;
        #pragma unroll
        for (int nt = 0; nt < 4; nt++) {
            const int colb = ct + nt * 8 + cb;
            *(float2*)&attnf[r0 * FPITCH + colb] =
                make_float2(cm[nt][0] * 0.125f, cm[nt][1] * 0.125f);
            *(float2*)&attnf[(r0 + 8) * FPITCH + colb] =
                make_float2(cm[nt][2] * 0.125f, cm[nt][3] * 0.125f);
        }
    }
    __syncthreads();

    // ---------------- row softmax + EPS (8 warps x 8 rows) ----------------
    #pragma unroll 1
    for (int rr = 0; rr < 8; rr++) {
        const int r = wid * 8 + rr;
        float v0 = attnf[r * FPITCH + lane];
        float v1 = attnf[r * FPITCH + lane + 32];
        float mx = fmaxf(v0, v1);
        #pragma unroll
        for (int o = 16; o > 0; o >>= 1)
            mx = fmaxf(mx, __shfl_xor_sync(0xffffffffu, mx, o));
        float e0 = __expf(v0 - mx);
        float e1 = __expf(v1 - mx);
        float s = e0 + e1;
        #pragma unroll
        for (int o = 16; o > 0; o >>= 1)
            s += __shfl_xor_sync(0xffffffffu, s, o);
        const float inv = 1.0f / s;
        attnf[r * FPITCH + lane]      = e0 * inv + 1e-6f;
        attnf[r * FPITCH + lane + 32] = e1 * inv + 1e-6f;
    }
    __syncthreads();

    // ---------------- column sums (4-way parallel) + normalize + store ----------------
    {
        const int col = tid & 63, q = tid >> 6;
        float s = 0.0f;
        #pragma unroll
        for (int l = 0; l < 16; l++) s += attnf[(q * 16 + l) * FPITCH + col];
        part[q][col] = s;
    }
    __syncthreads();
    if (tid < 64)
        csum_inv[tid] = 1.0f / (part[0][tid] + part[1][tid] + part[2][tid] + part[3][tid]);
    __syncthreads();

    {
        float* outb = out + (long)blockIdx.x * 4096;
        #pragma unroll
        for (int e = 0; e < 4; e++) {
            const int f4 = e * 256 + tid;
            const int l = f4 >> 4, m0 = (f4 & 15) * 4;
            float4 v = *(const float4*)&attnf[l * FPITCH + m0];
            v.x *= csum_inv[m0 + 0];
            v.y *= csum_inv[m0 + 1];
            v.z *= csum_inv[m0 + 2];
            v.w *= csum_inv[m0 + 3];
            *(float4*)&outb[l * 64 + m0] = v;
        }
    }
}

extern "C" void kernel_launch(void* const* d_in, const int* in_sizes, int n_in,
                              void* d_out, int out_size) {
    const float* yhat = (const float*)d_in[0];
    const float* y    = (const float*)d_in[1];
    const float* kmat = (const float*)d_in[2];
    const float* qmat = (const float*)d_in[3];
    float* out = (float*)d_out;

    const int N = in_sizes[1] / HDIM;
    const int grid = N / 64;                 // 1 segment per CTA

    split_kq_kernel<<<128, 256>>>(kmat, qmat);

    const size_t smem_bytes = SMEM_HALFS * sizeof(__half);   // 73728
    cudaFuncSetAttribute(cross_att_hmma8,
                         cudaFuncAttributeMaxDynamicSharedMemorySize, (int)smem_bytes);
    cudaFuncSetAttribute(cross_att_hmma8,
                         cudaFuncAttributePreferredSharedMemoryCarveout, 100);
    cross_att_hmma8<<<grid, 256, smem_bytes>>>(yhat, y, out);
}